// round 1
// baseline (speedup 1.0000x reference)
#include <cuda_runtime.h>

#define NS 20000
#define NT 20000
#define NE 500000
#define DIN 128
#define HID 64
#define NH 3
#define HC 192

#define OFF_XS  0
#define OFF_ATS (NS*HID)
#define OFF_XT  (OFF_ATS + NE*NH)
#define OFF_ATT (OFF_XT + NT*HID)

// ---------------- device scratch (static, no allocation) ----------------
__device__ __align__(16) float g_Hs[NS*HC];    // layer1: x_s@W1 ; layer2: X1s@Ws2
__device__ __align__(16) float g_Ht[NT*HC];    // layer1: x_t@W1 ; layer2: X1t@Ws2
__device__ __align__(16) float g_X1s[NS*HC];   // post-LN layer1 outputs
__device__ __align__(16) float g_X1t[NT*HC];
__device__ __align__(16) float g_P[NE*NH];     // exp(logit) buffer
__device__ __align__(16) float g_S[NS*NH];     // segment sums
__device__ __align__(16) float g_acc[NS*HC];   // scatter accumulator
__device__ __align__(16) float g_as_s[NS*NH];
__device__ __align__(16) float g_ad_s[NS*NH];
__device__ __align__(16) float g_as_t[NT*NH];
__device__ __align__(16) float g_ad_t[NT*NH];
__device__ __align__(16) float g_V1s[DIN*NH];
__device__ __align__(16) float g_V1d[DIN*NH];
__device__ __align__(16) float g_V2s[HC*NH];
__device__ __align__(16) float g_V2d[HC*NH];
__device__ float g_ce[2*NH];

// ---------------- prep: fold W@a into small projection vectors ----------------
__global__ void prep_kernel(const float* __restrict__ W1,
                            const float* __restrict__ as1, const float* __restrict__ ad1,
                            const float* __restrict__ Ws2, const float* __restrict__ Wd2,
                            const float* __restrict__ as2, const float* __restrict__ ad2,
                            const float* __restrict__ We1, const float* __restrict__ ae1,
                            const float* __restrict__ We2, const float* __restrict__ ae2) {
    int t = blockIdx.x * blockDim.x + threadIdx.x;
    const int nV1 = DIN*NH, nV2 = HC*NH;
    if (t < nV1) {
        int k = t/NH, h = t%NH; float s = 0.f;
        for (int j = 0; j < HID; j++) s += W1[k*HC + h*HID + j] * as1[h*HID + j];
        g_V1s[k*NH + h] = s; return;
    }
    t -= nV1;
    if (t < nV1) {
        int k = t/NH, h = t%NH; float s = 0.f;
        for (int j = 0; j < HID; j++) s += W1[k*HC + h*HID + j] * ad1[h*HID + j];
        g_V1d[k*NH + h] = s; return;
    }
    t -= nV1;
    if (t < nV2) {
        int k = t/NH, h = t%NH; float s = 0.f;
        for (int j = 0; j < HID; j++) s += Ws2[k*HC + h*HID + j] * as2[h*HID + j];
        g_V2s[k*NH + h] = s; return;
    }
    t -= nV2;
    if (t < nV2) {
        int k = t/NH, h = t%NH; float s = 0.f;
        for (int j = 0; j < HID; j++) s += Wd2[k*HC + h*HID + j] * ad2[h*HID + j];
        g_V2d[k*NH + h] = s; return;
    }
    t -= nV2;
    if (t < 2*NH) {
        int layer = t/NH, h = t%NH;
        const float* We = layer ? We2 : We1;
        const float* ae = layer ? ae2 : ae1;
        float s = 0.f;
        for (int j = 0; j < HID; j++) s += We[h*HID + j] * ae[h*HID + j];
        g_ce[layer*NH + h] = s;
    }
}

// ---------------- tiled fp32 GEMM: C[M x 192] = X[M x K] @ W[K x 192] ----------------
template<int K>
__global__ void gemm64_kernel(const float* __restrict__ X, const float* __restrict__ W,
                              float* __restrict__ C, int M) {
    __shared__ float As[16][64];
    __shared__ float Bs[16][64];
    const int tid = threadIdx.x;
    const int rowBase = blockIdx.x * 64;
    const int colBase = blockIdx.y * 64;
    const int tx = tid & 15, ty = tid >> 4;
    float acc[4][4] = {};

    const int la = tid * 4;
    const int am = la >> 4, ak = la & 15;   // A tile: row 0..63, k in {0,4,8,12}
    const int bk = la >> 6, bn = la & 63;   // B tile: k 0..15,  col multiple of 4

    for (int k0 = 0; k0 < K; k0 += 16) {
        float4 xa;
        int gr = rowBase + am;
        if (gr < M) xa = *reinterpret_cast<const float4*>(&X[(size_t)gr*K + k0 + ak]);
        else        xa = make_float4(0.f, 0.f, 0.f, 0.f);
        As[ak+0][am] = xa.x; As[ak+1][am] = xa.y; As[ak+2][am] = xa.z; As[ak+3][am] = xa.w;

        float4 wb = *reinterpret_cast<const float4*>(&W[(size_t)(k0+bk)*HC + colBase + bn]);
        Bs[bk][bn+0] = wb.x; Bs[bk][bn+1] = wb.y; Bs[bk][bn+2] = wb.z; Bs[bk][bn+3] = wb.w;
        __syncthreads();

        #pragma unroll
        for (int k = 0; k < 16; k++) {
            float a0 = As[k][ty*4+0], a1 = As[k][ty*4+1], a2 = As[k][ty*4+2], a3 = As[k][ty*4+3];
            float b0 = Bs[k][tx*4+0], b1 = Bs[k][tx*4+1], b2 = Bs[k][tx*4+2], b3 = Bs[k][tx*4+3];
            acc[0][0] += a0*b0; acc[0][1] += a0*b1; acc[0][2] += a0*b2; acc[0][3] += a0*b3;
            acc[1][0] += a1*b0; acc[1][1] += a1*b1; acc[1][2] += a1*b2; acc[1][3] += a1*b3;
            acc[2][0] += a2*b0; acc[2][1] += a2*b1; acc[2][2] += a2*b2; acc[2][3] += a2*b3;
            acc[3][0] += a3*b0; acc[3][1] += a3*b1; acc[3][2] += a3*b2; acc[3][3] += a3*b3;
        }
        __syncthreads();
    }
    #pragma unroll
    for (int i = 0; i < 4; i++) {
        int r = rowBase + ty*4 + i;
        if (r < M) {
            float4 v = make_float4(acc[i][0], acc[i][1], acc[i][2], acc[i][3]);
            *reinterpret_cast<float4*>(&C[(size_t)r*HC + colBase + tx*4]) = v;
        }
    }
}

// ---------------- per-node scalar attention projections (warp per node) ----------------
__global__ void proj_kernel(const float* __restrict__ X,
                            const float* __restrict__ Vs, const float* __restrict__ Vd,
                            float* __restrict__ as_o, float* __restrict__ ad_o,
                            int M, int K) {
    int gw = (blockIdx.x * blockDim.x + threadIdx.x) >> 5;
    int lane = threadIdx.x & 31;
    int nW = (gridDim.x * blockDim.x) >> 5;
    for (int n = gw; n < M; n += nW) {
        float s0=0.f,s1=0.f,s2=0.f,d0=0.f,d1=0.f,d2=0.f;
        for (int i = lane; i < K; i += 32) {
            float xv = __ldg(&X[(size_t)n*K + i]);
            s0 += xv * Vs[i*NH+0]; s1 += xv * Vs[i*NH+1]; s2 += xv * Vs[i*NH+2];
            d0 += xv * Vd[i*NH+0]; d1 += xv * Vd[i*NH+1]; d2 += xv * Vd[i*NH+2];
        }
        #pragma unroll
        for (int o = 16; o; o >>= 1) {
            s0 += __shfl_xor_sync(0xffffffffu, s0, o);
            s1 += __shfl_xor_sync(0xffffffffu, s1, o);
            s2 += __shfl_xor_sync(0xffffffffu, s2, o);
            d0 += __shfl_xor_sync(0xffffffffu, d0, o);
            d1 += __shfl_xor_sync(0xffffffffu, d1, o);
            d2 += __shfl_xor_sync(0xffffffffu, d2, o);
        }
        if (lane == 0) {
            as_o[n*NH+0] = s0; as_o[n*NH+1] = s1; as_o[n*NH+2] = s2;
            ad_o[n*NH+0] = d0; ad_o[n*NH+1] = d1; ad_o[n*NH+2] = d2;
        }
    }
}

// ---------------- edge pass 1: logits -> exp -> P, segment sums S ----------------
__global__ void edge_logit_kernel(const int* __restrict__ srcI, const int* __restrict__ dstI,
                                  const float* __restrict__ ea,
                                  const float* __restrict__ as, const float* __restrict__ ad,
                                  int layer, float* __restrict__ S) {
    int e = blockIdx.x * blockDim.x + threadIdx.x;
    if (e >= NE) return;
    int u = __ldg(&srcI[e]);
    int v = __ldg(&dstI[e]);
    float w = __ldg(&ea[e]);
    #pragma unroll
    for (int h = 0; h < NH; h++) {
        float l = __ldg(&as[u*NH+h]) + __ldg(&ad[v*NH+h]) + g_ce[layer*NH+h] * w;
        l = l > 0.f ? l : 0.2f * l;
        float p = __expf(l);
        g_P[e*NH+h] = p;
        atomicAdd(&S[v*NH+h], p);
    }
}

// ---------------- edge pass 2: normalize + weighted gather/scatter (warp per edge) ----------------
__global__ void edge_scatter_kernel(const int* __restrict__ srcI, const int* __restrict__ dstI,
                                    const float* __restrict__ Hval, float* __restrict__ acc,
                                    float* __restrict__ alpha_out) {
    int e = (blockIdx.x * blockDim.x + threadIdx.x) >> 5;
    int lane = threadIdx.x & 31;
    if (e >= NE) return;
    int u = __ldg(&srcI[e]);
    int v = __ldg(&dstI[e]);
    float w = 0.f;
    if (lane < NH) {
        w = g_P[e*NH+lane] / (g_S[v*NH+lane] + 1e-16f);
        if (alpha_out) alpha_out[e*NH+lane] = w;
    }
    float w0 = __shfl_sync(0xffffffffu, w, 0);
    float w1 = __shfl_sync(0xffffffffu, w, 1);
    float w2 = __shfl_sync(0xffffffffu, w, 2);
    const float* hrow = &Hval[(size_t)u * HC];
    float* arow = &acc[(size_t)v * HC];
    #pragma unroll
    for (int i = 0; i < 6; i++) {
        int c = lane + 32*i;
        float wg = (i < 2) ? w0 : ((i < 4) ? w1 : w2);
        atomicAdd(&arow[c], wg * __ldg(&hrow[c]));
    }
}

// ---------------- bias + leaky_relu(0.01) + LayerNorm(192) (warp per node) ----------------
__global__ void ln192_kernel(const float* __restrict__ acc, const float* __restrict__ bias,
                             const float* __restrict__ g, const float* __restrict__ be,
                             float* __restrict__ out, int M) {
    int n = (blockIdx.x * blockDim.x + threadIdx.x) >> 5;
    int lane = threadIdx.x & 31;
    if (n >= M) return;
    float v[6];
    float sum = 0.f;
    #pragma unroll
    for (int i = 0; i < 6; i++) {
        int c = lane + 32*i;
        float x = acc[(size_t)n*HC + c] + bias[c];
        x = x > 0.f ? x : 0.01f * x;
        v[i] = x; sum += x;
    }
    #pragma unroll
    for (int o = 16; o; o >>= 1) sum += __shfl_xor_sync(0xffffffffu, sum, o);
    float mean = sum * (1.f/HC);
    float var = 0.f;
    #pragma unroll
    for (int i = 0; i < 6; i++) { float d = v[i] - mean; var += d*d; }
    #pragma unroll
    for (int o = 16; o; o >>= 1) var += __shfl_xor_sync(0xffffffffu, var, o);
    float rstd = rsqrtf(var * (1.f/HC) + 1e-5f);
    #pragma unroll
    for (int i = 0; i < 6; i++) {
        int c = lane + 32*i;
        out[(size_t)n*HC + c] = (v[i] - mean) * rstd * g[c] + be[c];
    }
}

// ---------------- head-mean + bias + leaky_relu(0.01) + LayerNorm(64) (warp per node) ----------------
__global__ void ln64_kernel(const float* __restrict__ acc, const float* __restrict__ bias,
                            const float* __restrict__ g, const float* __restrict__ be,
                            float* __restrict__ out, int M) {
    int n = (blockIdx.x * blockDim.x + threadIdx.x) >> 5;
    int lane = threadIdx.x & 31;
    if (n >= M) return;
    float v[2];
    float sum = 0.f;
    #pragma unroll
    for (int j = 0; j < 2; j++) {
        int c = lane + 32*j;
        float x = (acc[(size_t)n*HC + c] + acc[(size_t)n*HC + 64 + c] + acc[(size_t)n*HC + 128 + c]) * (1.f/3.f)
                  + bias[c];
        x = x > 0.f ? x : 0.01f * x;
        v[j] = x; sum += x;
    }
    #pragma unroll
    for (int o = 16; o; o >>= 1) sum += __shfl_xor_sync(0xffffffffu, sum, o);
    float mean = sum * (1.f/HID);
    float var = 0.f;
    #pragma unroll
    for (int j = 0; j < 2; j++) { float d = v[j] - mean; var += d*d; }
    #pragma unroll
    for (int o = 16; o; o >>= 1) var += __shfl_xor_sync(0xffffffffu, var, o);
    float rstd = rsqrtf(var * (1.f/HID) + 1e-5f);
    #pragma unroll
    for (int j = 0; j < 2; j++) {
        int c = lane + 32*j;
        out[(size_t)n*HID + c] = (v[j] - mean) * rstd * g[c] + be[c];
    }
}

// ---------------- host ----------------
extern "C" void kernel_launch(void* const* d_in, const int* in_sizes, int n_in,
                              void* d_out, int out_size) {
    const float* x_s  = (const float*)d_in[0];
    const float* x_t  = (const float*)d_in[1];
    const int*   ei   = (const int*)  d_in[2];
    const float* ea   = (const float*)d_in[3];
    const float* W1   = (const float*)d_in[4];
    const float* a_s1 = (const float*)d_in[5];
    const float* a_d1 = (const float*)d_in[6];
    const float* We1  = (const float*)d_in[7];
    const float* a_e1 = (const float*)d_in[8];
    const float* b1   = (const float*)d_in[9];
    const float* Ws2  = (const float*)d_in[10];
    const float* Wd2  = (const float*)d_in[11];
    const float* a_s2 = (const float*)d_in[12];
    const float* a_d2 = (const float*)d_in[13];
    const float* We2  = (const float*)d_in[14];
    const float* a_e2 = (const float*)d_in[15];
    const float* b2   = (const float*)d_in[16];
    const float* g0   = (const float*)d_in[17];
    const float* be0  = (const float*)d_in[18];
    const float* g1   = (const float*)d_in[19];
    const float* be1  = (const float*)d_in[20];
    float* out = (float*)d_out;

    const int* srcI = ei;
    const int* dstI = ei + NE;

    float *pHs, *pHt, *pX1s, *pX1t, *pS, *pAcc;
    float *pAsS, *pAdS, *pAsT, *pAdT, *pV1s, *pV1d, *pV2s, *pV2d;
    cudaGetSymbolAddress((void**)&pHs,  g_Hs);
    cudaGetSymbolAddress((void**)&pHt,  g_Ht);
    cudaGetSymbolAddress((void**)&pX1s, g_X1s);
    cudaGetSymbolAddress((void**)&pX1t, g_X1t);
    cudaGetSymbolAddress((void**)&pS,   g_S);
    cudaGetSymbolAddress((void**)&pAcc, g_acc);
    cudaGetSymbolAddress((void**)&pAsS, g_as_s);
    cudaGetSymbolAddress((void**)&pAdS, g_ad_s);
    cudaGetSymbolAddress((void**)&pAsT, g_as_t);
    cudaGetSymbolAddress((void**)&pAdT, g_ad_t);
    cudaGetSymbolAddress((void**)&pV1s, g_V1s);
    cudaGetSymbolAddress((void**)&pV1d, g_V1d);
    cudaGetSymbolAddress((void**)&pV2s, g_V2s);
    cudaGetSymbolAddress((void**)&pV2d, g_V2d);

    const dim3 gemmGrid((NS + 63) / 64, 3);
    const int edgeBlocks1 = (NE + 255) / 256;          // 1 thread / edge
    const int edgeBlocks2 = (NE * 32 + 255) / 256;     // 1 warp / edge
    const int nodeWarpBlocks = (NS * 32 + 255) / 256;  // 1 warp / node

    // prep: fold projection vectors + edge constants
    prep_kernel<<<8, 256>>>(W1, a_s1, a_d1, Ws2, Wd2, a_s2, a_d2, We1, a_e1, We2, a_e2);

    // layer 1 hidden states + scalar logit parts
    gemm64_kernel<DIN><<<gemmGrid, 256>>>(x_s, W1, pHs, NS);
    gemm64_kernel<DIN><<<gemmGrid, 256>>>(x_t, W1, pHt, NT);
    proj_kernel<<<512, 256>>>(x_s, pV1s, pV1d, pAsS, pAdS, NS, DIN);
    proj_kernel<<<512, 256>>>(x_t, pV1s, pV1d, pAsT, pAdT, NT, DIN);

    // ---- layer 1, direction s->t (segment over dst) ----
    cudaMemsetAsync(pS, 0, NT*NH*sizeof(float));
    cudaMemsetAsync(pAcc, 0, (size_t)NT*HC*sizeof(float));
    edge_logit_kernel<<<edgeBlocks1, 256>>>(srcI, dstI, ea, pAsS, pAdT, 0, pS);
    edge_scatter_kernel<<<edgeBlocks2, 256>>>(srcI, dstI, pHs, pAcc, nullptr);
    ln192_kernel<<<nodeWarpBlocks, 256>>>(pAcc, b1, g0, be0, pX1t, NT);

    // ---- layer 1, direction t->s (segment over src) ----
    cudaMemsetAsync(pS, 0, NS*NH*sizeof(float));
    cudaMemsetAsync(pAcc, 0, (size_t)NS*HC*sizeof(float));
    edge_logit_kernel<<<edgeBlocks1, 256>>>(dstI, srcI, ea, pAsT, pAdS, 0, pS);
    edge_scatter_kernel<<<edgeBlocks2, 256>>>(dstI, srcI, pHt, pAcc, nullptr);
    ln192_kernel<<<nodeWarpBlocks, 256>>>(pAcc, b1, g0, be0, pX1s, NS);

    // layer 2 hidden states (only Ws2 GEMMs needed; Wd2 folded into V2d)
    gemm64_kernel<HC><<<gemmGrid, 256>>>(pX1s, Ws2, pHs, NS);
    gemm64_kernel<HC><<<gemmGrid, 256>>>(pX1t, Ws2, pHt, NT);
    proj_kernel<<<512, 256>>>(pX1s, pV2s, pV2d, pAsS, pAdS, NS, HC);
    proj_kernel<<<512, 256>>>(pX1t, pV2s, pV2d, pAsT, pAdT, NT, HC);

    // ---- layer 2, direction s->t ----
    cudaMemsetAsync(pS, 0, NT*NH*sizeof(float));
    cudaMemsetAsync(pAcc, 0, (size_t)NT*HC*sizeof(float));
    edge_logit_kernel<<<edgeBlocks1, 256>>>(srcI, dstI, ea, pAsS, pAdT, 1, pS);
    edge_scatter_kernel<<<edgeBlocks2, 256>>>(srcI, dstI, pHs, pAcc, out + OFF_ATT);
    ln64_kernel<<<nodeWarpBlocks, 256>>>(pAcc, b2, g1, be1, out + OFF_XT, NT);

    // ---- layer 2, direction t->s ----
    cudaMemsetAsync(pS, 0, NS*NH*sizeof(float));
    cudaMemsetAsync(pAcc, 0, (size_t)NS*HC*sizeof(float));
    edge_logit_kernel<<<edgeBlocks1, 256>>>(dstI, srcI, ea, pAsT, pAdS, 1, pS);
    edge_scatter_kernel<<<edgeBlocks2, 256>>>(dstI, srcI, pHt, pAcc, out + OFF_ATS);
    ln64_kernel<<<nodeWarpBlocks, 256>>>(pAcc, b2, g1, be1, out + OFF_XS, NS);
}

// round 2
// speedup vs baseline: 1.2560x; 1.2560x over previous
#include <cuda_runtime.h>

#define NS 20000
#define NT 20000
#define NE 500000
#define DIN 128
#define HID 64
#define NH 3
#define HC 192

#define OFF_XS  0
#define OFF_ATS (NS*HID)
#define OFF_XT  (OFF_ATS + NE*NH)
#define OFF_ATT (OFF_XT + NT*HID)

// ---------------- device scratch (static, no allocation) ----------------
__device__ __align__(16) float g_Hs[NS*HC];    // layer1: x_s@W1 ; layer2: X1s@Ws2
__device__ __align__(16) float g_Ht[NT*HC];
__device__ __align__(16) float g_X1s[NS*HC];   // post-LN layer1 outputs
__device__ __align__(16) float g_X1t[NT*HC];
__device__ __align__(16) float g_P[NE*NH];     // exp(logit) buffer
__device__ __align__(16) float g_as_s[NS*NH];
__device__ __align__(16) float g_ad_s[NS*NH];
__device__ __align__(16) float g_as_t[NT*NH];
__device__ __align__(16) float g_ad_t[NT*NH];
__device__ __align__(16) float g_V1s[DIN*NH];
__device__ __align__(16) float g_V1d[DIN*NH];
__device__ __align__(16) float g_V2s[HC*NH];
__device__ __align__(16) float g_V2d[HC*NH];
__device__ float g_ce[2*NH];

// CSR structures (built fresh every launch)
__device__ int g_cntT[NT];
__device__ int g_cntS[NS];
__device__ int g_offT[NT];
__device__ int g_offS[NS];
__device__ int g_curT[NT];
__device__ int g_curS[NS];
__device__ int g_eidT[NE];
__device__ int g_nbrT[NE];
__device__ int g_eidS[NE];
__device__ int g_nbrS[NE];

// ---------------- prep: fold W@a into small projection vectors ----------------
__global__ void prep_kernel(const float* __restrict__ W1,
                            const float* __restrict__ as1, const float* __restrict__ ad1,
                            const float* __restrict__ Ws2, const float* __restrict__ Wd2,
                            const float* __restrict__ as2, const float* __restrict__ ad2,
                            const float* __restrict__ We1, const float* __restrict__ ae1,
                            const float* __restrict__ We2, const float* __restrict__ ae2) {
    int t = blockIdx.x * blockDim.x + threadIdx.x;
    const int nV1 = DIN*NH, nV2 = HC*NH;
    if (t < nV1) {
        int k = t/NH, h = t%NH; float s = 0.f;
        for (int j = 0; j < HID; j++) s += W1[k*HC + h*HID + j] * as1[h*HID + j];
        g_V1s[k*NH + h] = s; return;
    }
    t -= nV1;
    if (t < nV1) {
        int k = t/NH, h = t%NH; float s = 0.f;
        for (int j = 0; j < HID; j++) s += W1[k*HC + h*HID + j] * ad1[h*HID + j];
        g_V1d[k*NH + h] = s; return;
    }
    t -= nV1;
    if (t < nV2) {
        int k = t/NH, h = t%NH; float s = 0.f;
        for (int j = 0; j < HID; j++) s += Ws2[k*HC + h*HID + j] * as2[h*HID + j];
        g_V2s[k*NH + h] = s; return;
    }
    t -= nV2;
    if (t < nV2) {
        int k = t/NH, h = t%NH; float s = 0.f;
        for (int j = 0; j < HID; j++) s += Wd2[k*HC + h*HID + j] * ad2[h*HID + j];
        g_V2d[k*NH + h] = s; return;
    }
    t -= nV2;
    if (t < 2*NH) {
        int layer = t/NH, h = t%NH;
        const float* We = layer ? We2 : We1;
        const float* ae = layer ? ae2 : ae1;
        float s = 0.f;
        for (int j = 0; j < HID; j++) s += We[h*HID + j] * ae[h*HID + j];
        g_ce[layer*NH + h] = s;
    }
}

// ---------------- CSR build ----------------
__global__ void hist_kernel(const int* __restrict__ srcI, const int* __restrict__ dstI) {
    int e = blockIdx.x * blockDim.x + threadIdx.x;
    if (e >= NE) return;
    atomicAdd(&g_cntT[__ldg(&dstI[e])], 1);
    atomicAdd(&g_cntS[__ldg(&srcI[e])], 1);
}

__global__ void scan_kernel() {
    // blockIdx.x == 0 -> T side ; 1 -> S side
    int* cnt = blockIdx.x ? g_cntS : g_cntT;
    int* off = blockIdx.x ? g_offS : g_offT;
    int* cur = blockIdx.x ? g_curS : g_curT;
    const int n = blockIdx.x ? NS : NT;
    __shared__ int partial[1024];
    const int t = threadIdx.x;
    const int chunk = (n + 1023) / 1024;
    int start = t * chunk;
    int s = 0;
    for (int j = 0; j < chunk; j++) {
        int idx = start + j;
        if (idx < n) s += cnt[idx];
    }
    partial[t] = s;
    __syncthreads();
    // Hillis-Steele inclusive scan
    for (int d = 1; d < 1024; d <<= 1) {
        int v = (t >= d) ? partial[t - d] : 0;
        __syncthreads();
        partial[t] += v;
        __syncthreads();
    }
    int run = partial[t] - s;   // exclusive prefix for this chunk
    for (int j = 0; j < chunk; j++) {
        int idx = start + j;
        if (idx < n) {
            off[idx] = run;
            cur[idx] = run;
            run += cnt[idx];
        }
    }
}

__global__ void fill_kernel(const int* __restrict__ srcI, const int* __restrict__ dstI) {
    int e = blockIdx.x * blockDim.x + threadIdx.x;
    if (e >= NE) return;
    int u = __ldg(&srcI[e]);
    int v = __ldg(&dstI[e]);
    int p1 = atomicAdd(&g_curT[v], 1);
    g_eidT[p1] = e; g_nbrT[p1] = u;
    int p2 = atomicAdd(&g_curS[u], 1);
    g_eidS[p2] = e; g_nbrS[p2] = v;
}

// ---------------- tiled fp32 GEMM: C[M x 192] = X[M x K] @ W[K x 192] ----------------
template<int K>
__global__ void gemm64_kernel(const float* __restrict__ X, const float* __restrict__ W,
                              float* __restrict__ C, int M) {
    __shared__ float As[16][64];
    __shared__ float Bs[16][64];
    const int tid = threadIdx.x;
    const int rowBase = blockIdx.x * 64;
    const int colBase = blockIdx.y * 64;
    const int tx = tid & 15, ty = tid >> 4;
    float acc[4][4] = {};

    const int la = tid * 4;
    const int am = la >> 4, ak = la & 15;
    const int bk = la >> 6, bn = la & 63;

    for (int k0 = 0; k0 < K; k0 += 16) {
        float4 xa;
        int gr = rowBase + am;
        if (gr < M) xa = *reinterpret_cast<const float4*>(&X[(size_t)gr*K + k0 + ak]);
        else        xa = make_float4(0.f, 0.f, 0.f, 0.f);
        As[ak+0][am] = xa.x; As[ak+1][am] = xa.y; As[ak+2][am] = xa.z; As[ak+3][am] = xa.w;

        float4 wb = *reinterpret_cast<const float4*>(&W[(size_t)(k0+bk)*HC + colBase + bn]);
        Bs[bk][bn+0] = wb.x; Bs[bk][bn+1] = wb.y; Bs[bk][bn+2] = wb.z; Bs[bk][bn+3] = wb.w;
        __syncthreads();

        #pragma unroll
        for (int k = 0; k < 16; k++) {
            float a0 = As[k][ty*4+0], a1 = As[k][ty*4+1], a2 = As[k][ty*4+2], a3 = As[k][ty*4+3];
            float b0 = Bs[k][tx*4+0], b1 = Bs[k][tx*4+1], b2 = Bs[k][tx*4+2], b3 = Bs[k][tx*4+3];
            acc[0][0] += a0*b0; acc[0][1] += a0*b1; acc[0][2] += a0*b2; acc[0][3] += a0*b3;
            acc[1][0] += a1*b0; acc[1][1] += a1*b1; acc[1][2] += a1*b2; acc[1][3] += a1*b3;
            acc[2][0] += a2*b0; acc[2][1] += a2*b1; acc[2][2] += a2*b2; acc[2][3] += a2*b3;
            acc[3][0] += a3*b0; acc[3][1] += a3*b1; acc[3][2] += a3*b2; acc[3][3] += a3*b3;
        }
        __syncthreads();
    }
    #pragma unroll
    for (int i = 0; i < 4; i++) {
        int r = rowBase + ty*4 + i;
        if (r < M) {
            float4 v = make_float4(acc[i][0], acc[i][1], acc[i][2], acc[i][3]);
            *reinterpret_cast<float4*>(&C[(size_t)r*HC + colBase + tx*4]) = v;
        }
    }
}

// ---------------- per-node scalar attention projections (warp per node) ----------------
__global__ void proj_kernel(const float* __restrict__ X,
                            const float* __restrict__ Vs, const float* __restrict__ Vd,
                            float* __restrict__ as_o, float* __restrict__ ad_o,
                            int M, int K) {
    int gw = (blockIdx.x * blockDim.x + threadIdx.x) >> 5;
    int lane = threadIdx.x & 31;
    int nW = (gridDim.x * blockDim.x) >> 5;
    for (int n = gw; n < M; n += nW) {
        float s0=0.f,s1=0.f,s2=0.f,d0=0.f,d1=0.f,d2=0.f;
        for (int i = lane; i < K; i += 32) {
            float xv = __ldg(&X[(size_t)n*K + i]);
            s0 += xv * Vs[i*NH+0]; s1 += xv * Vs[i*NH+1]; s2 += xv * Vs[i*NH+2];
            d0 += xv * Vd[i*NH+0]; d1 += xv * Vd[i*NH+1]; d2 += xv * Vd[i*NH+2];
        }
        #pragma unroll
        for (int o = 16; o; o >>= 1) {
            s0 += __shfl_xor_sync(0xffffffffu, s0, o);
            s1 += __shfl_xor_sync(0xffffffffu, s1, o);
            s2 += __shfl_xor_sync(0xffffffffu, s2, o);
            d0 += __shfl_xor_sync(0xffffffffu, d0, o);
            d1 += __shfl_xor_sync(0xffffffffu, d1, o);
            d2 += __shfl_xor_sync(0xffffffffu, d2, o);
        }
        if (lane == 0) {
            as_o[n*NH+0] = s0; as_o[n*NH+1] = s1; as_o[n*NH+2] = s2;
            ad_o[n*NH+0] = d0; ad_o[n*NH+1] = d1; ad_o[n*NH+2] = d2;
        }
    }
}

// ---------------- fused per-node aggregation: logits + softmax + gather + LN ----------------
// warp per destination node. CONCAT=true -> layer1 (LN over 192, out stride HC)
//                            CONCAT=false -> layer2 (head-mean, LN over 64, out stride HID)
template<bool CONCAT>
__global__ void agg_kernel(const int* __restrict__ off, const int* __restrict__ cnt,
                           const int* __restrict__ eidA, const int* __restrict__ nbrA,
                           const float* __restrict__ asrc, const float* __restrict__ adst,
                           const float* __restrict__ ea, int layer,
                           const float* __restrict__ Hval,
                           const float* __restrict__ bias,
                           const float* __restrict__ g, const float* __restrict__ be,
                           float* __restrict__ out, float* __restrict__ alpha_out, int M) {
    int n = (blockIdx.x * blockDim.x + threadIdx.x) >> 5;
    int lane = threadIdx.x & 31;
    if (n >= M) return;

    const int r0 = __ldg(&off[n]);
    const int deg = __ldg(&cnt[n]);
    const float ce0 = g_ce[layer*NH+0], ce1 = g_ce[layer*NH+1], ce2 = g_ce[layer*NH+2];
    const float ad0 = __ldg(&adst[n*NH+0]);
    const float ad1 = __ldg(&adst[n*NH+1]);
    const float ad2 = __ldg(&adst[n*NH+2]);

    // pass 1: logits -> exp -> P (by edge id), accumulate softmax denominators
    float s0 = 0.f, s1 = 0.f, s2 = 0.f;
    for (int j = lane; j < deg; j += 32) {
        int e = __ldg(&eidA[r0+j]);
        int u = __ldg(&nbrA[r0+j]);
        float w = __ldg(&ea[e]);
        float l0 = __ldg(&asrc[u*NH+0]) + ad0 + ce0*w;
        float l1 = __ldg(&asrc[u*NH+1]) + ad1 + ce1*w;
        float l2 = __ldg(&asrc[u*NH+2]) + ad2 + ce2*w;
        l0 = l0 > 0.f ? l0 : 0.2f*l0;
        l1 = l1 > 0.f ? l1 : 0.2f*l1;
        l2 = l2 > 0.f ? l2 : 0.2f*l2;
        float p0 = __expf(l0), p1 = __expf(l1), p2 = __expf(l2);
        g_P[e*NH+0] = p0; g_P[e*NH+1] = p1; g_P[e*NH+2] = p2;
        s0 += p0; s1 += p1; s2 += p2;
    }
    #pragma unroll
    for (int o = 16; o; o >>= 1) {
        s0 += __shfl_xor_sync(0xffffffffu, s0, o);
        s1 += __shfl_xor_sync(0xffffffffu, s1, o);
        s2 += __shfl_xor_sync(0xffffffffu, s2, o);
    }
    const float inv0 = 1.f / (s0 + 1e-16f);
    const float inv1 = 1.f / (s1 + 1e-16f);
    const float inv2 = 1.f / (s2 + 1e-16f);
    __syncwarp();

    // pass 2: weighted gather-accumulate (whole warp per edge; 192 cols)
    float acc[6] = {0.f, 0.f, 0.f, 0.f, 0.f, 0.f};
    #pragma unroll 2
    for (int j = 0; j < deg; j++) {
        int e = __ldg(&eidA[r0+j]);
        int u = __ldg(&nbrA[r0+j]);
        float w0 = __ldg(&g_P[e*NH+0]) * inv0;
        float w1 = __ldg(&g_P[e*NH+1]) * inv1;
        float w2 = __ldg(&g_P[e*NH+2]) * inv2;
        if (!CONCAT && lane == 0) {   // layer2 exports alpha in original edge order
            alpha_out[e*NH+0] = w0;
            alpha_out[e*NH+1] = w1;
            alpha_out[e*NH+2] = w2;
        }
        const float* hr = &Hval[(size_t)u * HC];
        acc[0] += w0 * __ldg(&hr[lane      ]);
        acc[1] += w0 * __ldg(&hr[lane +  32]);
        acc[2] += w1 * __ldg(&hr[lane +  64]);
        acc[3] += w1 * __ldg(&hr[lane +  96]);
        acc[4] += w2 * __ldg(&hr[lane + 128]);
        acc[5] += w2 * __ldg(&hr[lane + 160]);
    }

    if (CONCAT) {
        // bias + leaky(0.01) + LayerNorm over 192
        float v[6]; float sum = 0.f;
        #pragma unroll
        for (int i = 0; i < 6; i++) {
            int c = lane + 32*i;
            float x = acc[i] + __ldg(&bias[c]);
            x = x > 0.f ? x : 0.01f*x;
            v[i] = x; sum += x;
        }
        #pragma unroll
        for (int o = 16; o; o >>= 1) sum += __shfl_xor_sync(0xffffffffu, sum, o);
        float mean = sum * (1.f/HC);
        float var = 0.f;
        #pragma unroll
        for (int i = 0; i < 6; i++) { float d = v[i] - mean; var += d*d; }
        #pragma unroll
        for (int o = 16; o; o >>= 1) var += __shfl_xor_sync(0xffffffffu, var, o);
        float rstd = rsqrtf(var * (1.f/HC) + 1e-5f);
        #pragma unroll
        for (int i = 0; i < 6; i++) {
            int c = lane + 32*i;
            out[(size_t)n*HC + c] = (v[i] - mean) * rstd * __ldg(&g[c]) + __ldg(&be[c]);
        }
    } else {
        // head-mean + bias + leaky(0.01) + LayerNorm over 64
        float v[2]; float sum = 0.f;
        #pragma unroll
        for (int j = 0; j < 2; j++) {
            int c = lane + 32*j;
            float x = (acc[j] + acc[j+2] + acc[j+4]) * (1.f/3.f) + __ldg(&bias[c]);
            x = x > 0.f ? x : 0.01f*x;
            v[j] = x; sum += x;
        }
        #pragma unroll
        for (int o = 16; o; o >>= 1) sum += __shfl_xor_sync(0xffffffffu, sum, o);
        float mean = sum * (1.f/HID);
        float var = 0.f;
        #pragma unroll
        for (int j = 0; j < 2; j++) { float d = v[j] - mean; var += d*d; }
        #pragma unroll
        for (int o = 16; o; o >>= 1) var += __shfl_xor_sync(0xffffffffu, var, o);
        float rstd = rsqrtf(var * (1.f/HID) + 1e-5f);
        #pragma unroll
        for (int j = 0; j < 2; j++) {
            int c = lane + 32*j;
            out[(size_t)n*HID + c] = (v[j] - mean) * rstd * __ldg(&g[c]) + __ldg(&be[c]);
        }
    }
}

// ---------------- host ----------------
extern "C" void kernel_launch(void* const* d_in, const int* in_sizes, int n_in,
                              void* d_out, int out_size) {
    const float* x_s  = (const float*)d_in[0];
    const float* x_t  = (const float*)d_in[1];
    const int*   ei   = (const int*)  d_in[2];
    const float* ea   = (const float*)d_in[3];
    const float* W1   = (const float*)d_in[4];
    const float* a_s1 = (const float*)d_in[5];
    const float* a_d1 = (const float*)d_in[6];
    const float* We1  = (const float*)d_in[7];
    const float* a_e1 = (const float*)d_in[8];
    const float* b1   = (const float*)d_in[9];
    const float* Ws2  = (const float*)d_in[10];
    const float* Wd2  = (const float*)d_in[11];
    const float* a_s2 = (const float*)d_in[12];
    const float* a_d2 = (const float*)d_in[13];
    const float* We2  = (const float*)d_in[14];
    const float* a_e2 = (const float*)d_in[15];
    const float* b2   = (const float*)d_in[16];
    const float* g0   = (const float*)d_in[17];
    const float* be0  = (const float*)d_in[18];
    const float* g1   = (const float*)d_in[19];
    const float* be1  = (const float*)d_in[20];
    float* out = (float*)d_out;

    const int* srcI = ei;
    const int* dstI = ei + NE;

    float *pHs, *pHt, *pX1s, *pX1t;
    float *pAsS, *pAdS, *pAsT, *pAdT, *pV1s, *pV1d, *pV2s, *pV2d;
    int *pCntT, *pCntS, *pOffT, *pOffS, *pEidT, *pNbrT, *pEidS, *pNbrS;
    cudaGetSymbolAddress((void**)&pHs,  g_Hs);
    cudaGetSymbolAddress((void**)&pHt,  g_Ht);
    cudaGetSymbolAddress((void**)&pX1s, g_X1s);
    cudaGetSymbolAddress((void**)&pX1t, g_X1t);
    cudaGetSymbolAddress((void**)&pAsS, g_as_s);
    cudaGetSymbolAddress((void**)&pAdS, g_ad_s);
    cudaGetSymbolAddress((void**)&pAsT, g_as_t);
    cudaGetSymbolAddress((void**)&pAdT, g_ad_t);
    cudaGetSymbolAddress((void**)&pV1s, g_V1s);
    cudaGetSymbolAddress((void**)&pV1d, g_V1d);
    cudaGetSymbolAddress((void**)&pV2s, g_V2s);
    cudaGetSymbolAddress((void**)&pV2d, g_V2d);
    cudaGetSymbolAddress((void**)&pCntT, g_cntT);
    cudaGetSymbolAddress((void**)&pCntS, g_cntS);
    cudaGetSymbolAddress((void**)&pOffT, g_offT);
    cudaGetSymbolAddress((void**)&pOffS, g_offS);
    cudaGetSymbolAddress((void**)&pEidT, g_eidT);
    cudaGetSymbolAddress((void**)&pNbrT, g_nbrT);
    cudaGetSymbolAddress((void**)&pEidS, g_eidS);
    cudaGetSymbolAddress((void**)&pNbrS, g_nbrS);

    const dim3 gemmGrid((NS + 63) / 64, 3);
    const int edgeBlocks = (NE + 255) / 256;
    const int nodeWarpBlocks = (NS * 32 + 255) / 256;

    // CSR build (shared by both layers)
    cudaMemsetAsync(pCntT, 0, NT * sizeof(int));
    cudaMemsetAsync(pCntS, 0, NS * sizeof(int));
    hist_kernel<<<edgeBlocks, 256>>>(srcI, dstI);
    scan_kernel<<<2, 1024>>>();
    fill_kernel<<<edgeBlocks, 256>>>(srcI, dstI);

    // prep + layer 1 hidden states + scalar logit parts
    prep_kernel<<<8, 256>>>(W1, a_s1, a_d1, Ws2, Wd2, a_s2, a_d2, We1, a_e1, We2, a_e2);
    gemm64_kernel<DIN><<<gemmGrid, 256>>>(x_s, W1, pHs, NS);
    gemm64_kernel<DIN><<<gemmGrid, 256>>>(x_t, W1, pHt, NT);
    proj_kernel<<<512, 256>>>(x_s, pV1s, pV1d, pAsS, pAdS, NS, DIN);
    proj_kernel<<<512, 256>>>(x_t, pV1s, pV1d, pAsT, pAdT, NT, DIN);

    // layer 1: s->t (group by dst), then t->s (group by src)
    agg_kernel<true><<<nodeWarpBlocks, 256>>>(pOffT, pCntT, pEidT, pNbrT,
                                              pAsS, pAdT, ea, 0, pHs,
                                              b1, g0, be0, pX1t, nullptr, NT);
    agg_kernel<true><<<nodeWarpBlocks, 256>>>(pOffS, pCntS, pEidS, pNbrS,
                                              pAsT, pAdS, ea, 0, pHt,
                                              b1, g0, be0, pX1s, nullptr, NS);

    // layer 2 hidden states + scalar parts
    gemm64_kernel<HC><<<gemmGrid, 256>>>(pX1s, Ws2, pHs, NS);
    gemm64_kernel<HC><<<gemmGrid, 256>>>(pX1t, Ws2, pHt, NT);
    proj_kernel<<<512, 256>>>(pX1s, pV2s, pV2d, pAsS, pAdS, NS, HC);
    proj_kernel<<<512, 256>>>(pX1t, pV2s, pV2d, pAsT, pAdT, NT, HC);

    // layer 2: s->t and t->s (exports alpha + 64-wide LN outputs)
    agg_kernel<false><<<nodeWarpBlocks, 256>>>(pOffT, pCntT, pEidT, pNbrT,
                                               pAsS, pAdT, ea, 1, pHs,
                                               b2, g1, be1, out + OFF_XT, out + OFF_ATT, NT);
    agg_kernel<false><<<nodeWarpBlocks, 256>>>(pOffS, pCntS, pEidS, pNbrS,
                                               pAsT, pAdS, ea, 1, pHt,
                                               b2, g1, be1, out + OFF_XS, out + OFF_ATS, NS);
}

// round 3
// speedup vs baseline: 1.6981x; 1.3520x over previous
#include <cuda_runtime.h>
#include <cstdint>

#define NS 20000
#define NT 20000
#define NE 500000
#define DIN 128
#define HID 64
#define NH 3
#define HC 192

#define OFF_XS  0
#define OFF_ATS (NS*HID)
#define OFF_XT  (OFF_ATS + NE*NH)
#define OFF_ATT (OFF_XT + NT*HID)

// ---------------- device scratch (static, no allocation) ----------------
__device__ __align__(16) float g_Hs[NS*HC];
__device__ __align__(16) float g_Ht[NT*HC];
__device__ __align__(16) float g_X1s[NS*HC];
__device__ __align__(16) float g_X1t[NT*HC];
__device__ __align__(16) float g_P[3*NE];      // planar by CSR position
__device__ __align__(16) float g_as_s[NS*NH];
__device__ __align__(16) float g_ad_s[NS*NH];
__device__ __align__(16) float g_as_t[NT*NH];
__device__ __align__(16) float g_ad_t[NT*NH];
__device__ __align__(16) float g_V1s[DIN*NH];
__device__ __align__(16) float g_V1d[DIN*NH];
__device__ __align__(16) float g_V2s[HC*NH];
__device__ __align__(16) float g_V2d[HC*NH];
__device__ float g_ce[2*NH];

// CSR
__device__ int g_cntT[NT];
__device__ int g_cntS[NS];
__device__ int g_offT[NT];
__device__ int g_offS[NS];
__device__ int g_curT[NT];
__device__ int g_curS[NS];
__device__ int g_eidT[NE];
__device__ int g_nbrT[NE];
__device__ int g_eidS[NE];
__device__ int g_nbrS[NE];

__device__ __forceinline__ uint32_t f2tf(float x) {
    uint32_t r;
    asm("cvt.rna.tf32.f32 %0, %1;" : "=r"(r) : "f"(x));
    return r;
}

// ---------------- prep: fold W@a, warp per output ----------------
__global__ void prep_kernel(const float* __restrict__ W1,
                            const float* __restrict__ as1, const float* __restrict__ ad1,
                            const float* __restrict__ Ws2, const float* __restrict__ Wd2,
                            const float* __restrict__ as2, const float* __restrict__ ad2,
                            const float* __restrict__ We1, const float* __restrict__ ae1,
                            const float* __restrict__ We2, const float* __restrict__ ae2) {
    int w = (blockIdx.x * blockDim.x + threadIdx.x) >> 5;
    int lane = threadIdx.x & 31;
    const int nV1 = DIN*NH, nV2 = HC*NH;
    const float* Wm; const float* av; float* dstp; int k, h;
    if (w < nV1)                   { k = w/NH; h = w%NH; Wm = W1;  av = as1; dstp = &g_V1s[k*NH+h]; }
    else if ((w -= nV1) < nV1)     { k = w/NH; h = w%NH; Wm = W1;  av = ad1; dstp = &g_V1d[k*NH+h]; }
    else if ((w -= nV1) < nV2)     { k = w/NH; h = w%NH; Wm = Ws2; av = as2; dstp = &g_V2s[k*NH+h]; }
    else if ((w -= nV2) < nV2)     { k = w/NH; h = w%NH; Wm = Wd2; av = ad2; dstp = &g_V2d[k*NH+h]; }
    else if ((w -= nV2) < 2*NH)    { int layer = w/NH; h = w%NH; k = 0;
                                     Wm = layer ? We2 : We1; av = layer ? ae2 : ae1;
                                     dstp = &g_ce[layer*NH+h]; }
    else return;
    float s = Wm[k*HC + h*HID + lane] * av[h*HID + lane]
            + Wm[k*HC + h*HID + lane + 32] * av[h*HID + lane + 32];
    #pragma unroll
    for (int o = 16; o; o >>= 1) s += __shfl_xor_sync(0xffffffffu, s, o);
    if (lane == 0) *dstp = s;
}

// ---------------- CSR build ----------------
__global__ void hist_kernel(const int* __restrict__ srcI, const int* __restrict__ dstI) {
    int e = blockIdx.x * blockDim.x + threadIdx.x;
    if (e >= NE) return;
    atomicAdd(&g_cntT[__ldg(&dstI[e])], 1);
    atomicAdd(&g_cntS[__ldg(&srcI[e])], 1);
}

__global__ void scan_kernel() {
    int* cnt = blockIdx.x ? g_cntS : g_cntT;
    int* off = blockIdx.x ? g_offS : g_offT;
    int* cur = blockIdx.x ? g_curS : g_curT;
    const int n = blockIdx.x ? NS : NT;
    __shared__ int partial[1024];
    const int t = threadIdx.x;
    const int chunk = (n + 1023) / 1024;
    int start = t * chunk;
    int s = 0;
    for (int j = 0; j < chunk; j++) {
        int idx = start + j;
        if (idx < n) s += cnt[idx];
    }
    partial[t] = s;
    __syncthreads();
    for (int d = 1; d < 1024; d <<= 1) {
        int v = (t >= d) ? partial[t - d] : 0;
        __syncthreads();
        partial[t] += v;
        __syncthreads();
    }
    int run = partial[t] - s;
    for (int j = 0; j < chunk; j++) {
        int idx = start + j;
        if (idx < n) {
            off[idx] = run;
            cur[idx] = run;
            run += cnt[idx];
        }
    }
}

__global__ void fill_kernel(const int* __restrict__ srcI, const int* __restrict__ dstI) {
    int e = blockIdx.x * blockDim.x + threadIdx.x;
    if (e >= NE) return;
    int u = __ldg(&srcI[e]);
    int v = __ldg(&dstI[e]);
    int p1 = atomicAdd(&g_curT[v], 1);
    g_eidT[p1] = e; g_nbrT[p1] = u;
    int p2 = atomicAdd(&g_curS[u], 1);
    g_eidS[p2] = e; g_nbrS[p2] = v;
}

// ---------------- tf32 tensor-core GEMM: C[M x 192] = X[M x K] @ W[K x 192] ----------------
// block: 128 threads (4 warps); tile M=64, N=64, Ktile=32; warp w -> rows 16w..16w+15
template<int K>
__global__ void gemm_tf32_kernel(const float* __restrict__ X, const float* __restrict__ W,
                                 float* __restrict__ C, int M) {
    __shared__ uint32_t As[64][36];   // padded: conflict-free A-frag reads
    __shared__ uint32_t Bs[32][72];   // padded: conflict-free B-frag reads
    const int tid = threadIdx.x;
    const int warp = tid >> 5;
    const int lane = tid & 31;
    const int q = lane >> 2;   // 0..7 (groupID)
    const int m = lane & 3;    // 0..3 (threadID in group)
    const int rowBase = blockIdx.x * 64;
    const int colBase = blockIdx.y * 64;

    float c[8][4];
    #pragma unroll
    for (int i = 0; i < 8; i++)
        #pragma unroll
        for (int j = 0; j < 4; j++) c[i][j] = 0.f;

    for (int k0 = 0; k0 < K; k0 += 32) {
        // A tile: 64 rows x 32 cols
        #pragma unroll
        for (int i = 0; i < 4; i++) {
            int r = (tid >> 3) + 16*i;
            int f4c = (tid & 7) * 4;
            int gr = rowBase + r;
            float4 v = make_float4(0.f, 0.f, 0.f, 0.f);
            if (gr < M) v = *reinterpret_cast<const float4*>(&X[(size_t)gr*K + k0 + f4c]);
            As[r][f4c+0] = f2tf(v.x); As[r][f4c+1] = f2tf(v.y);
            As[r][f4c+2] = f2tf(v.z); As[r][f4c+3] = f2tf(v.w);
        }
        // B tile: 32 k-rows x 64 cols
        #pragma unroll
        for (int i = 0; i < 4; i++) {
            int kk = (tid >> 4) + 8*i;
            int f4c = (tid & 15) * 4;
            float4 v = *reinterpret_cast<const float4*>(&W[(size_t)(k0+kk)*HC + colBase + f4c]);
            Bs[kk][f4c+0] = f2tf(v.x); Bs[kk][f4c+1] = f2tf(v.y);
            Bs[kk][f4c+2] = f2tf(v.z); Bs[kk][f4c+3] = f2tf(v.w);
        }
        __syncthreads();

        #pragma unroll
        for (int kk = 0; kk < 32; kk += 8) {
            uint32_t a0 = As[warp*16 + q    ][kk + m    ];
            uint32_t a1 = As[warp*16 + q + 8][kk + m    ];
            uint32_t a2 = As[warp*16 + q    ][kk + m + 4];
            uint32_t a3 = As[warp*16 + q + 8][kk + m + 4];
            #pragma unroll
            for (int nt = 0; nt < 8; nt++) {
                uint32_t b0 = Bs[kk + m    ][nt*8 + q];
                uint32_t b1 = Bs[kk + m + 4][nt*8 + q];
                asm volatile(
                    "mma.sync.aligned.m16n8k8.row.col.f32.tf32.tf32.f32 "
                    "{%0,%1,%2,%3}, {%4,%5,%6,%7}, {%8,%9}, {%0,%1,%2,%3};"
                    : "+f"(c[nt][0]), "+f"(c[nt][1]), "+f"(c[nt][2]), "+f"(c[nt][3])
                    : "r"(a0), "r"(a1), "r"(a2), "r"(a3), "r"(b0), "r"(b1));
            }
        }
        __syncthreads();
    }

    int r0 = rowBase + warp*16 + q;
    #pragma unroll
    for (int nt = 0; nt < 8; nt++) {
        int col = colBase + nt*8 + 2*m;
        if (r0 < M)
            *reinterpret_cast<float2*>(&C[(size_t)r0*HC + col]) = make_float2(c[nt][0], c[nt][1]);
        if (r0 + 8 < M)
            *reinterpret_cast<float2*>(&C[(size_t)(r0+8)*HC + col]) = make_float2(c[nt][2], c[nt][3]);
    }
}

// ---------------- per-node scalar attention projections (warp per node, shared V) ----------------
__global__ void proj_kernel(const float* __restrict__ X,
                            const float* __restrict__ Vs, const float* __restrict__ Vd,
                            float* __restrict__ as_o, float* __restrict__ ad_o,
                            int M, int K) {
    __shared__ float sV[2*HC*NH];
    for (int i = threadIdx.x; i < K*NH; i += blockDim.x) {
        sV[i] = Vs[i];
        sV[HC*NH + i] = Vd[i];
    }
    __syncthreads();
    int n = (blockIdx.x * blockDim.x + threadIdx.x) >> 5;
    int lane = threadIdx.x & 31;
    if (n >= M) return;
    float s0=0.f,s1=0.f,s2=0.f,d0=0.f,d1=0.f,d2=0.f;
    #pragma unroll
    for (int i = lane; i < K; i += 32) {
        float xv = __ldg(&X[(size_t)n*K + i]);
        s0 += xv * sV[i*NH+0]; s1 += xv * sV[i*NH+1]; s2 += xv * sV[i*NH+2];
        d0 += xv * sV[HC*NH + i*NH+0]; d1 += xv * sV[HC*NH + i*NH+1]; d2 += xv * sV[HC*NH + i*NH+2];
    }
    #pragma unroll
    for (int o = 16; o; o >>= 1) {
        s0 += __shfl_xor_sync(0xffffffffu, s0, o);
        s1 += __shfl_xor_sync(0xffffffffu, s1, o);
        s2 += __shfl_xor_sync(0xffffffffu, s2, o);
        d0 += __shfl_xor_sync(0xffffffffu, d0, o);
        d1 += __shfl_xor_sync(0xffffffffu, d1, o);
        d2 += __shfl_xor_sync(0xffffffffu, d2, o);
    }
    if (lane == 0) {
        as_o[n*NH+0] = s0; as_o[n*NH+1] = s1; as_o[n*NH+2] = s2;
        ad_o[n*NH+0] = d0; ad_o[n*NH+1] = d1; ad_o[n*NH+2] = d2;
    }
}

// ---------------- fused aggregation: logits + softmax + float4 gather + LN ----------------
// warp per destination node. Vector lane layout:
//   chunk A: cols 4*lane..4*lane+3 (head = lane/16), all lanes
//   chunk B: cols 128+4*lane..    (head 2), lanes 0..15
template<bool CONCAT>
__global__ void agg_kernel(const int* __restrict__ off, const int* __restrict__ cnt,
                           const int* __restrict__ eidA, const int* __restrict__ nbrA,
                           const float* __restrict__ asrc, const float* __restrict__ adst,
                           const float* __restrict__ ea, int layer,
                           const float* __restrict__ Hval,
                           const float* __restrict__ bias,
                           const float* __restrict__ g, const float* __restrict__ be,
                           float* __restrict__ out, float* __restrict__ alpha_out, int M) {
    int n = (blockIdx.x * blockDim.x + threadIdx.x) >> 5;
    int lane = threadIdx.x & 31;
    if (n >= M) return;

    const int r0 = __ldg(&off[n]);
    const int deg = __ldg(&cnt[n]);
    const float ce0 = g_ce[layer*NH+0], ce1 = g_ce[layer*NH+1], ce2 = g_ce[layer*NH+2];
    const float ad0 = __ldg(&adst[n*NH+0]);
    const float ad1 = __ldg(&adst[n*NH+1]);
    const float ad2 = __ldg(&adst[n*NH+2]);

    // pass 1: logits -> exp (stored by CSR position, planar) + denominators
    float s0 = 0.f, s1 = 0.f, s2 = 0.f;
    for (int j = lane; j < deg; j += 32) {
        int idx = r0 + j;
        int e = __ldg(&eidA[idx]);
        int u = __ldg(&nbrA[idx]);
        float w = __ldg(&ea[e]);
        float l0 = __ldg(&asrc[u*NH+0]) + ad0 + ce0*w;
        float l1 = __ldg(&asrc[u*NH+1]) + ad1 + ce1*w;
        float l2 = __ldg(&asrc[u*NH+2]) + ad2 + ce2*w;
        l0 = l0 > 0.f ? l0 : 0.2f*l0;
        l1 = l1 > 0.f ? l1 : 0.2f*l1;
        l2 = l2 > 0.f ? l2 : 0.2f*l2;
        float p0 = __expf(l0), p1 = __expf(l1), p2 = __expf(l2);
        g_P[idx] = p0; g_P[NE + idx] = p1; g_P[2*NE + idx] = p2;
        s0 += p0; s1 += p1; s2 += p2;
    }
    #pragma unroll
    for (int o = 16; o; o >>= 1) {
        s0 += __shfl_xor_sync(0xffffffffu, s0, o);
        s1 += __shfl_xor_sync(0xffffffffu, s1, o);
        s2 += __shfl_xor_sync(0xffffffffu, s2, o);
    }
    const float inv0 = 1.f / (s0 + 1e-16f);
    const float inv1 = 1.f / (s1 + 1e-16f);
    const float inv2 = 1.f / (s2 + 1e-16f);
    __syncwarp();

    // pass 2: weighted float4 gather
    const float4* base = reinterpret_cast<const float4*>(Hval);
    const bool lo = lane < 16;
    float4 accA = make_float4(0.f, 0.f, 0.f, 0.f);
    float4 accB = make_float4(0.f, 0.f, 0.f, 0.f);
    #pragma unroll 2
    for (int j = 0; j < deg; j++) {
        int idx = r0 + j;
        int e = __ldg(&eidA[idx]);
        int u = __ldg(&nbrA[idx]);
        float w0 = __ldg(&g_P[idx]) * inv0;
        float w1 = __ldg(&g_P[NE + idx]) * inv1;
        float w2 = __ldg(&g_P[2*NE + idx]) * inv2;
        if (!CONCAT && lane < 3) {
            float wsel = lane == 0 ? w0 : (lane == 1 ? w1 : w2);
            alpha_out[(size_t)e*NH + lane] = wsel;
        }
        const float4* hr = base + (size_t)u * 48;
        float4 fa = __ldg(&hr[lane]);
        float wA = lo ? w0 : w1;
        accA.x += wA*fa.x; accA.y += wA*fa.y; accA.z += wA*fa.z; accA.w += wA*fa.w;
        if (lo) {
            float4 fb = __ldg(&hr[32 + lane]);
            accB.x += w2*fb.x; accB.y += w2*fb.y; accB.z += w2*fb.z; accB.w += w2*fb.w;
        }
    }

    if (CONCAT) {
        // bias + leaky(0.01) + LN(192); lane holds cols 4l.. and (lo) 128+4l..
        float4 bA = __ldg(reinterpret_cast<const float4*>(&bias[4*lane]));
        float vA[4], vB[4];
        vA[0] = accA.x + bA.x; vA[1] = accA.y + bA.y; vA[2] = accA.z + bA.z; vA[3] = accA.w + bA.w;
        float sum = 0.f;
        #pragma unroll
        for (int i = 0; i < 4; i++) {
            vA[i] = vA[i] > 0.f ? vA[i] : 0.01f*vA[i];
            sum += vA[i];
        }
        if (lo) {
            float4 bB = __ldg(reinterpret_cast<const float4*>(&bias[128 + 4*lane]));
            vB[0] = accB.x + bB.x; vB[1] = accB.y + bB.y; vB[2] = accB.z + bB.z; vB[3] = accB.w + bB.w;
            #pragma unroll
            for (int i = 0; i < 4; i++) {
                vB[i] = vB[i] > 0.f ? vB[i] : 0.01f*vB[i];
                sum += vB[i];
            }
        }
        #pragma unroll
        for (int o = 16; o; o >>= 1) sum += __shfl_xor_sync(0xffffffffu, sum, o);
        float mean = sum * (1.f/HC);
        float var = 0.f;
        #pragma unroll
        for (int i = 0; i < 4; i++) { float d = vA[i] - mean; var += d*d; }
        if (lo) {
            #pragma unroll
            for (int i = 0; i < 4; i++) { float d = vB[i] - mean; var += d*d; }
        }
        #pragma unroll
        for (int o = 16; o; o >>= 1) var += __shfl_xor_sync(0xffffffffu, var, o);
        float rstd = rsqrtf(var * (1.f/HC) + 1e-5f);

        float4* out4 = reinterpret_cast<float4*>(out) + (size_t)n * 48;
        float4 gA = __ldg(reinterpret_cast<const float4*>(&g[4*lane]));
        float4 eA = __ldg(reinterpret_cast<const float4*>(&be[4*lane]));
        float4 rA;
        rA.x = (vA[0]-mean)*rstd*gA.x + eA.x;
        rA.y = (vA[1]-mean)*rstd*gA.y + eA.y;
        rA.z = (vA[2]-mean)*rstd*gA.z + eA.z;
        rA.w = (vA[3]-mean)*rstd*gA.w + eA.w;
        out4[lane] = rA;
        if (lo) {
            float4 gB = __ldg(reinterpret_cast<const float4*>(&g[128 + 4*lane]));
            float4 eB = __ldg(reinterpret_cast<const float4*>(&be[128 + 4*lane]));
            float4 rB;
            rB.x = (vB[0]-mean)*rstd*gB.x + eB.x;
            rB.y = (vB[1]-mean)*rstd*gB.y + eB.y;
            rB.z = (vB[2]-mean)*rstd*gB.z + eB.z;
            rB.w = (vB[3]-mean)*rstd*gB.w + eB.w;
            out4[32 + lane] = rB;
        }
    } else {
        // head-mean + bias + leaky(0.01) + LN(64); lanes 0..15 own 4 cols each
        float h1x = __shfl_down_sync(0xffffffffu, accA.x, 16);
        float h1y = __shfl_down_sync(0xffffffffu, accA.y, 16);
        float h1z = __shfl_down_sync(0xffffffffu, accA.z, 16);
        float h1w = __shfl_down_sync(0xffffffffu, accA.w, 16);
        float v[4]; float sum = 0.f;
        if (lo) {
            float4 bA = __ldg(reinterpret_cast<const float4*>(&bias[4*lane]));
            v[0] = (accA.x + h1x + accB.x) * (1.f/3.f) + bA.x;
            v[1] = (accA.y + h1y + accB.y) * (1.f/3.f) + bA.y;
            v[2] = (accA.z + h1z + accB.z) * (1.f/3.f) + bA.z;
            v[3] = (accA.w + h1w + accB.w) * (1.f/3.f) + bA.w;
            #pragma unroll
            for (int i = 0; i < 4; i++) {
                v[i] = v[i] > 0.f ? v[i] : 0.01f*v[i];
                sum += v[i];
            }
        }
        // reduce within lower/upper 16-lane halves (offsets <= 8 stay in half)
        #pragma unroll
        for (int o = 8; o; o >>= 1) sum += __shfl_xor_sync(0xffffffffu, sum, o);
        float mean = sum * (1.f/HID);
        float var = 0.f;
        if (lo) {
            #pragma unroll
            for (int i = 0; i < 4; i++) { float d = v[i] - mean; var += d*d; }
        }
        #pragma unroll
        for (int o = 8; o; o >>= 1) var += __shfl_xor_sync(0xffffffffu, var, o);
        float rstd = rsqrtf(var * (1.f/HID) + 1e-5f);
        if (lo) {
            float4 gA = __ldg(reinterpret_cast<const float4*>(&g[4*lane]));
            float4 eA = __ldg(reinterpret_cast<const float4*>(&be[4*lane]));
            float4 r;
            r.x = (v[0]-mean)*rstd*gA.x + eA.x;
            r.y = (v[1]-mean)*rstd*gA.y + eA.y;
            r.z = (v[2]-mean)*rstd*gA.z + eA.z;
            r.w = (v[3]-mean)*rstd*gA.w + eA.w;
            reinterpret_cast<float4*>(out)[(size_t)n*16 + lane] = r;
        }
    }
}

// ---------------- host ----------------
extern "C" void kernel_launch(void* const* d_in, const int* in_sizes, int n_in,
                              void* d_out, int out_size) {
    const float* x_s  = (const float*)d_in[0];
    const float* x_t  = (const float*)d_in[1];
    const int*   ei   = (const int*)  d_in[2];
    const float* ea   = (const float*)d_in[3];
    const float* W1   = (const float*)d_in[4];
    const float* a_s1 = (const float*)d_in[5];
    const float* a_d1 = (const float*)d_in[6];
    const float* We1  = (const float*)d_in[7];
    const float* a_e1 = (const float*)d_in[8];
    const float* b1   = (const float*)d_in[9];
    const float* Ws2  = (const float*)d_in[10];
    const float* Wd2  = (const float*)d_in[11];
    const float* a_s2 = (const float*)d_in[12];
    const float* a_d2 = (const float*)d_in[13];
    const float* We2  = (const float*)d_in[14];
    const float* a_e2 = (const float*)d_in[15];
    const float* b2   = (const float*)d_in[16];
    const float* g0   = (const float*)d_in[17];
    const float* be0  = (const float*)d_in[18];
    const float* g1   = (const float*)d_in[19];
    const float* be1  = (const float*)d_in[20];
    float* out = (float*)d_out;

    const int* srcI = ei;
    const int* dstI = ei + NE;

    float *pHs, *pHt, *pX1s, *pX1t;
    float *pAsS, *pAdS, *pAsT, *pAdT, *pV1s, *pV1d, *pV2s, *pV2d;
    int *pCntT, *pCntS, *pOffT, *pOffS, *pEidT, *pNbrT, *pEidS, *pNbrS;
    cudaGetSymbolAddress((void**)&pHs,  g_Hs);
    cudaGetSymbolAddress((void**)&pHt,  g_Ht);
    cudaGetSymbolAddress((void**)&pX1s, g_X1s);
    cudaGetSymbolAddress((void**)&pX1t, g_X1t);
    cudaGetSymbolAddress((void**)&pAsS, g_as_s);
    cudaGetSymbolAddress((void**)&pAdS, g_ad_s);
    cudaGetSymbolAddress((void**)&pAsT, g_as_t);
    cudaGetSymbolAddress((void**)&pAdT, g_ad_t);
    cudaGetSymbolAddress((void**)&pV1s, g_V1s);
    cudaGetSymbolAddress((void**)&pV1d, g_V1d);
    cudaGetSymbolAddress((void**)&pV2s, g_V2s);
    cudaGetSymbolAddress((void**)&pV2d, g_V2d);
    cudaGetSymbolAddress((void**)&pCntT, g_cntT);
    cudaGetSymbolAddress((void**)&pCntS, g_cntS);
    cudaGetSymbolAddress((void**)&pOffT, g_offT);
    cudaGetSymbolAddress((void**)&pOffS, g_offS);
    cudaGetSymbolAddress((void**)&pEidT, g_eidT);
    cudaGetSymbolAddress((void**)&pNbrT, g_nbrT);
    cudaGetSymbolAddress((void**)&pEidS, g_eidS);
    cudaGetSymbolAddress((void**)&pNbrS, g_nbrS);

    const dim3 gemmGrid((NS + 63) / 64, 3);
    const int edgeBlocks = (NE + 255) / 256;
    const int nodeWarpBlocks = (NS * 32 + 255) / 256;
    const int prepBlocks = ((DIN*NH*2 + HC*NH*2 + 2*NH) * 32 + 255) / 256;

    // CSR build (shared by both layers)
    cudaMemsetAsync(pCntT, 0, NT * sizeof(int));
    cudaMemsetAsync(pCntS, 0, NS * sizeof(int));
    hist_kernel<<<edgeBlocks, 256>>>(srcI, dstI);
    scan_kernel<<<2, 1024>>>();
    fill_kernel<<<edgeBlocks, 256>>>(srcI, dstI);

    // prep + layer 1
    prep_kernel<<<prepBlocks, 256>>>(W1, a_s1, a_d1, Ws2, Wd2, a_s2, a_d2, We1, a_e1, We2, a_e2);
    gemm_tf32_kernel<DIN><<<gemmGrid, 128>>>(x_s, W1, pHs, NS);
    gemm_tf32_kernel<DIN><<<gemmGrid, 128>>>(x_t, W1, pHt, NT);
    proj_kernel<<<nodeWarpBlocks, 256>>>(x_s, pV1s, pV1d, pAsS, pAdS, NS, DIN);
    proj_kernel<<<nodeWarpBlocks, 256>>>(x_t, pV1s, pV1d, pAsT, pAdT, NT, DIN);

    agg_kernel<true><<<nodeWarpBlocks, 256>>>(pOffT, pCntT, pEidT, pNbrT,
                                              pAsS, pAdT, ea, 0, pHs,
                                              b1, g0, be0, pX1t, nullptr, NT);
    agg_kernel<true><<<nodeWarpBlocks, 256>>>(pOffS, pCntS, pEidS, pNbrS,
                                              pAsT, pAdS, ea, 0, pHt,
                                              b1, g0, be0, pX1s, nullptr, NS);

    // layer 2
    gemm_tf32_kernel<HC><<<gemmGrid, 128>>>(pX1s, Ws2, pHs, NS);
    gemm_tf32_kernel<HC><<<gemmGrid, 128>>>(pX1t, Ws2, pHt, NT);
    proj_kernel<<<nodeWarpBlocks, 256>>>(pX1s, pV2s, pV2d, pAsS, pAdS, NS, HC);
    proj_kernel<<<nodeWarpBlocks, 256>>>(pX1t, pV2s, pV2d, pAsT, pAdT, NT, HC);

    agg_kernel<false><<<nodeWarpBlocks, 256>>>(pOffT, pCntT, pEidT, pNbrT,
                                               pAsS, pAdT, ea, 1, pHs,
                                               b2, g1, be1, out + OFF_XT, out + OFF_ATT, NT);
    agg_kernel<false><<<nodeWarpBlocks, 256>>>(pOffS, pCntS, pEidS, pNbrS,
                                               pAsT, pAdS, ea, 1, pHt,
                                               b2, g1, be1, out + OFF_XS, out + OFF_ATS, NS);
}